// round 7
// baseline (speedup 1.0000x reference)
#include <cuda_runtime.h>
#include <cuda_fp16.h>
#include <cstdint>

// Problem constants (fixed shapes from reference)
#define N_NODES 32768      // B*S = 64*512
#define IN_F    256
#define OUT_F   256
#define NBASES  3
#define N_EDGES 262144
#define TCOLS   768        // NBASES * OUT_F

// Scratch
__device__ __half g_t[(size_t)N_NODES * TCOLS];           // t = h @ bases (fp16), 48MB
__device__ __half g_Ah[(size_t)N_NODES * IN_F];           // fp16 text
__device__ __half g_Bh[(size_t)NBASES * IN_F * OUT_F];    // fp16 bases [b][k][n]
// Counting-sort scratch (sort edges by dst)
__device__ int g_cnt[N_NODES];
__device__ int g_start[N_NODES];
__device__ int g_cursor[N_NODES];
__device__ int g_ssrc[N_EDGES];
__device__ int g_srel[N_EDGES];

__device__ __forceinline__ uint32_t smem_u32(const void* p) {
    uint32_t a;
    asm("{ .reg .u64 t; cvta.to.shared.u64 t, %1; cvt.u32.u64 %0, t; }" : "=r"(a) : "l"(p));
    return a;
}

// ---------------------------------------------------------------------------
// fp16 convert
// ---------------------------------------------------------------------------
__global__ void split_h_kernel(const float* __restrict__ src, __half* __restrict__ dh, int n4)
{
    int i = blockIdx.x * blockDim.x + threadIdx.x;
    if (i >= n4) return;
    float4 v = ((const float4*)src)[i];
    ((__half2*)dh)[2 * i + 0] = __halves2half2(__float2half_rn(v.x), __float2half_rn(v.y));
    ((__half2*)dh)[2 * i + 1] = __halves2half2(__float2half_rn(v.z), __float2half_rn(v.w));
}

// ---------------------------------------------------------------------------
// Counting sort of edges by dst: zero -> histogram -> scan -> scatter
// ---------------------------------------------------------------------------
__global__ void zero_cnt_kernel()
{
    int i = blockIdx.x * blockDim.x + threadIdx.x;
    if (i < N_NODES) g_cnt[i] = 0;
}

__global__ void hist_kernel(const int* __restrict__ dst)
{
    int e = blockIdx.x * blockDim.x + threadIdx.x;
    if (e < N_EDGES) atomicAdd(&g_cnt[dst[e]], 1);
}

__global__ void __launch_bounds__(1024) scan_kernel()
{
    __shared__ int part[1024];
    const int tid = threadIdx.x;
    const int base = tid * 32;
    int local[32];
    int s = 0;
    #pragma unroll
    for (int i = 0; i < 32; i++) { local[i] = g_cnt[base + i]; s += local[i]; }
    part[tid] = s;
    __syncthreads();
    // Hillis-Steele inclusive scan over 1024 partials
    for (int off = 1; off < 1024; off <<= 1) {
        int t = (tid >= off) ? part[tid - off] : 0;
        __syncthreads();
        part[tid] += t;
        __syncthreads();
    }
    int run = part[tid] - s;   // exclusive prefix of this thread's segment
    #pragma unroll
    for (int i = 0; i < 32; i++) {
        g_start[base + i] = run;
        g_cursor[base + i] = run;
        run += local[i];
    }
}

__global__ void scatter_kernel(const int* __restrict__ src, const int* __restrict__ dst,
                               const int* __restrict__ rel)
{
    int e = blockIdx.x * blockDim.x + threadIdx.x;
    if (e >= N_EDGES) return;
    int pos = atomicAdd(&g_cursor[dst[e]], 1);
    g_ssrc[pos] = src[e];
    g_srel[pos] = rel[e];
}

// ---------------------------------------------------------------------------
// Tensor-core GEMM (legacy mma.sync; tcgen05 rejected by compute_103 stage).
// C[m, n] = A[m,:] . B[:,n], n = b*256+o.  Single term fp16.
// CTA: 128x64, K chunked by 64 (4 chunks -> half the syncs), 2-stage cp.async,
// 3 CTAs/SM. 8 warps as 4(M) x 2(N): warp tile 32x32, mma.m16n8k16.
// ---------------------------------------------------------------------------
#define SAROW 144u                 // 64 halfs + 16B pad (9*16B: conflict-free ldsm)
#define SBROW 144u                 // 64 halfs + 16B pad
#define OFF_B  18432u              // 128*144
#define STAGE_B 27648u             // A 18432 | B 9216
#define GEMM_SMEM (2 * 27648)

__device__ __forceinline__ void ldm_x4(uint32_t* r, uint32_t addr) {
    asm volatile("ldmatrix.sync.aligned.m8n8.x4.shared.b16 {%0,%1,%2,%3}, [%4];"
                 : "=r"(r[0]), "=r"(r[1]), "=r"(r[2]), "=r"(r[3]) : "r"(addr));
}
__device__ __forceinline__ void ldm_x4t(uint32_t* r, uint32_t addr) {
    asm volatile("ldmatrix.sync.aligned.m8n8.x4.trans.shared.b16 {%0,%1,%2,%3}, [%4];"
                 : "=r"(r[0]), "=r"(r[1]), "=r"(r[2]), "=r"(r[3]) : "r"(addr));
}
__device__ __forceinline__ void mma16816(float* c, const uint32_t* a, const uint32_t* b) {
    asm volatile("mma.sync.aligned.m16n8k16.row.col.f32.f16.f16.f32 "
                 "{%0,%1,%2,%3}, {%4,%5,%6,%7}, {%8,%9}, {%0,%1,%2,%3};"
                 : "+f"(c[0]), "+f"(c[1]), "+f"(c[2]), "+f"(c[3])
                 : "r"(a[0]), "r"(a[1]), "r"(a[2]), "r"(a[3]), "r"(b[0]), "r"(b[1]));
}
__device__ __forceinline__ void cpa16(uint32_t dst, const void* src) {
    asm volatile("cp.async.cg.shared.global [%0], [%1], 16;" :: "r"(dst), "l"(src) : "memory");
}

__device__ __forceinline__ void gemm_load_chunk(uint32_t sb, int s, int m0, int n0, int c, int tid)
{
    const uint32_t so = sb + (uint32_t)s * STAGE_B;
    const int k0 = c << 6;
    const int b  = n0 >> 8;              // basis index (n0 multiple of 64)
    const int nc = n0 & 255;
    // A: 128 rows x 64 halfs (8 x 16B per row) -> 1024 chunks, 4 per thread
    #pragma unroll
    for (int i = 0; i < 4; i++) {
        int idx = tid + (i << 8);
        int row = idx >> 3, ch = idx & 7;
        size_t goff = (size_t)(m0 + row) * IN_F + k0 + (ch << 3);
        cpa16(so + (uint32_t)row * SAROW + (uint32_t)(ch << 4), g_Ah + goff);
    }
    // B: 64 k-rows x 64 halfs (8 x 16B per row) -> 512 chunks, 2 per thread
    #pragma unroll
    for (int i = 0; i < 2; i++) {
        int idx = tid + (i << 8);
        int row = idx >> 3, ch = idx & 7;
        size_t goff = (size_t)b * (IN_F * OUT_F) + (size_t)(k0 + row) * OUT_F + nc + (ch << 3);
        cpa16(so + OFF_B + (uint32_t)row * SBROW + (uint32_t)(ch << 4), g_Bh + goff);
    }
    asm volatile("cp.async.commit_group;" ::: "memory");
}

__global__ void __launch_bounds__(256, 3) gemm_tc_kernel()
{
    extern __shared__ char smem[];
    const uint32_t sb = smem_u32(smem);
    const int tid  = threadIdx.x;
    const int wid  = tid >> 5;
    const int lane = tid & 31;
    const int wm = wid >> 1;          // 0..3 (M)
    const int wn = wid & 1;           // 0..1 (N)
    const int n0 = blockIdx.x << 6;
    const int m0 = blockIdx.y << 7;

    const uint32_t a_lane = (uint32_t)((lane & 15) * SAROW + (lane >> 4) * 16) + (uint32_t)(wm * 32) * SAROW;
    const uint32_t b_lane = (uint32_t)((lane & 15) * SBROW + (lane >> 4) * 16) + (uint32_t)(wn * 64);

    float acc[2][4][4];
    #pragma unroll
    for (int mt = 0; mt < 2; mt++)
        #pragma unroll
        for (int nt = 0; nt < 4; nt++)
            #pragma unroll
            for (int q = 0; q < 4; q++) acc[mt][nt][q] = 0.0f;

    gemm_load_chunk(sb, 0, m0, n0, 0, tid);

    for (int c = 0; c < 4; c++) {
        if (c + 1 < 4) {
            gemm_load_chunk(sb, (c + 1) & 1, m0, n0, c + 1, tid);
            asm volatile("cp.async.wait_group 1;" ::: "memory");
        } else {
            asm volatile("cp.async.wait_group 0;" ::: "memory");
        }
        __syncthreads();

        const uint32_t so = sb + (uint32_t)(c & 1) * STAGE_B;
        #pragma unroll
        for (int kk = 0; kk < 4; kk++) {
            uint32_t ah[2][4];
            #pragma unroll
            for (int mt = 0; mt < 2; mt++)
                ldm_x4(ah[mt], so + a_lane + (uint32_t)(mt * 16) * SAROW + (uint32_t)(kk * 32));
            #pragma unroll
            for (int p = 0; p < 2; p++) {
                uint32_t bh[4];
                ldm_x4t(bh, so + OFF_B + b_lane + (uint32_t)(kk * 16) * SBROW + (uint32_t)(p * 32));
                #pragma unroll
                for (int s = 0; s < 2; s++) {
                    const int nt = p * 2 + s;
                    #pragma unroll
                    for (int mt = 0; mt < 2; mt++)
                        mma16816(acc[mt][nt], ah[mt], bh + 2 * s);
                }
            }
        }
        __syncthreads();
    }

    // Epilogue: write C tile to g_t as fp16
    #pragma unroll
    for (int mt = 0; mt < 2; mt++) {
        int row0 = m0 + wm * 32 + mt * 16 + (lane >> 2);
        #pragma unroll
        for (int nt = 0; nt < 4; nt++) {
            int col = n0 + wn * 32 + nt * 8 + (lane & 3) * 2;
            __half* p0 = g_t + (size_t)row0 * TCOLS + col;
            __half* p1 = p0 + 8 * TCOLS;
            *(__half2*)p0 = __floats2half2_rn(acc[mt][nt][0], acc[mt][nt][1]);
            *(__half2*)p1 = __floats2half2_rn(acc[mt][nt][2], acc[mt][nt][3]);
        }
    }
}

// ---------------------------------------------------------------------------
// Node aggregation: one warp per destination node. Walks the dst-sorted edge
// list, gathers t[src] (coalesced), accumulates in registers, writes
// relu(acc + bias) once. No atomics, no init pass, no relu pass.
// ---------------------------------------------------------------------------
__device__ __forceinline__ void acc8(float* a, uint4 q, float c)
{
    float2 v;
    v = __half22float2(*(__half2*)&q.x); a[0] = fmaf(c, v.x, a[0]); a[1] = fmaf(c, v.y, a[1]);
    v = __half22float2(*(__half2*)&q.y); a[2] = fmaf(c, v.x, a[2]); a[3] = fmaf(c, v.y, a[3]);
    v = __half22float2(*(__half2*)&q.z); a[4] = fmaf(c, v.x, a[4]); a[5] = fmaf(c, v.y, a[5]);
    v = __half22float2(*(__half2*)&q.w); a[6] = fmaf(c, v.x, a[6]); a[7] = fmaf(c, v.y, a[7]);
}

__global__ void __launch_bounds__(256) node_agg_kernel(
    const float* __restrict__ comp, const float* __restrict__ bias,
    float* __restrict__ out)
{
    const int d    = blockIdx.x * 8 + (threadIdx.x >> 5);
    const int lane = threadIdx.x & 31;

    float acc[8];
    {
        float4 b0 = *(const float4*)(bias + 8 * lane);
        float4 b1 = *(const float4*)(bias + 8 * lane + 4);
        acc[0] = b0.x; acc[1] = b0.y; acc[2] = b0.z; acc[3] = b0.w;
        acc[4] = b1.x; acc[5] = b1.y; acc[6] = b1.z; acc[7] = b1.w;
    }

    const int beg = g_start[d];
    const int num = g_cnt[d];
    for (int i = 0; i < num; i++) {
        const int s = g_ssrc[beg + i];
        const int r = g_srel[beg + i];
        const float c0 = __ldg(comp + r * NBASES + 0);
        const float c1 = __ldg(comp + r * NBASES + 1);
        const float c2 = __ldg(comp + r * NBASES + 2);
        const uint4* tp = (const uint4*)(g_t + (size_t)s * TCOLS);  // 96 x 16B per row
        uint4 q0 = __ldg(tp + lane);        // basis 0, cols 8*lane..8*lane+7
        uint4 q1 = __ldg(tp + 32 + lane);   // basis 1
        uint4 q2 = __ldg(tp + 64 + lane);   // basis 2
        acc8(acc, q0, c0);
        acc8(acc, q1, c1);
        acc8(acc, q2, c2);
    }

    float4 o0 = make_float4(fmaxf(acc[0], 0.f), fmaxf(acc[1], 0.f), fmaxf(acc[2], 0.f), fmaxf(acc[3], 0.f));
    float4 o1 = make_float4(fmaxf(acc[4], 0.f), fmaxf(acc[5], 0.f), fmaxf(acc[6], 0.f), fmaxf(acc[7], 0.f));
    float* op = out + (size_t)d * OUT_F + 8 * lane;
    *(float4*)op = o0;
    *(float4*)(op + 4) = o1;
}

// ---------------------------------------------------------------------------
// Launch
// ---------------------------------------------------------------------------
extern "C" void kernel_launch(void* const* d_in, const int* in_sizes, int n_in,
                              void* d_out, int out_size)
{
    const float* text  = (const float*)d_in[0];   // [64,512,256]
    const int*   src   = (const int*)  d_in[1];   // [E]
    const int*   dst   = (const int*)  d_in[2];   // [E]
    const int*   rel   = (const int*)  d_in[3];   // [E]
    const float* bases = (const float*)d_in[4];   // [3,256,256]
    const float* comp  = (const float*)d_in[5];   // [40,3]
    const float* bias  = (const float*)d_in[6];   // [256]
    float* out = (float*)d_out;                   // [64,512,256]

    cudaFuncSetAttribute(gemm_tc_kernel, cudaFuncAttributeMaxDynamicSharedMemorySize, GEMM_SMEM);

    // 1. fp16 converts
    __half *ah, *bh;
    cudaGetSymbolAddress((void**)&ah, g_Ah);
    cudaGetSymbolAddress((void**)&bh, g_Bh);
    split_h_kernel<<<(N_NODES * IN_F / 4 + 255) / 256, 256>>>(text, ah, N_NODES * IN_F / 4);
    split_h_kernel<<<(NBASES * IN_F * OUT_F / 4 + 255) / 256, 256>>>(bases, bh, NBASES * IN_F * OUT_F / 4);

    // 2. counting sort of edges by dst
    zero_cnt_kernel<<<N_NODES / 256, 256>>>();
    hist_kernel<<<N_EDGES / 256, 256>>>(dst);
    scan_kernel<<<1, 1024>>>();
    scatter_kernel<<<N_EDGES / 256, 256>>>(src, dst, rel);

    // 3. t = text @ bases on the tensor pipe (single-term fp16)
    gemm_tc_kernel<<<dim3(TCOLS / 64, N_NODES / 128), 256, GEMM_SMEM>>>();

    // 4. per-node gather + combine + bias + ReLU (no atomics)
    node_agg_kernel<<<N_NODES / 8, 256>>>(comp, bias, out);
}

// round 8
// speedup vs baseline: 1.1314x; 1.1314x over previous
#include <cuda_runtime.h>
#include <cuda_fp16.h>
#include <cstdint>

// Problem constants (fixed shapes from reference)
#define N_NODES 32768      // B*S = 64*512
#define IN_F    256
#define OUT_F   256
#define NBASES  3
#define N_EDGES 262144
#define KDIM    768        // NBASES * IN_F: GEMM K dimension

// Scratch
__device__ __half g_h[(size_t)N_NODES * IN_F];            // fp16 text (16MB, L2-resident)
__device__ __half g_z[(size_t)N_NODES * KDIM];            // aggregated z[d][b][i] fp16, 48MB
__device__ __half g_Bh[(size_t)KDIM * OUT_F];             // fp16 bases stacked [(b,i)][o]
// Counting-sort scratch (sort edges by dst)
__device__ int g_cnt[N_NODES];
__device__ int g_start[N_NODES];
__device__ int g_cursor[N_NODES];
__device__ int g_ssrc[N_EDGES];
__device__ int g_srel[N_EDGES];

__device__ __forceinline__ uint32_t smem_u32(const void* p) {
    uint32_t a;
    asm("{ .reg .u64 t; cvta.to.shared.u64 t, %1; cvt.u32.u64 %0, t; }" : "=r"(a) : "l"(p));
    return a;
}

// ---------------------------------------------------------------------------
// fp16 convert
// ---------------------------------------------------------------------------
__global__ void split_h_kernel(const float* __restrict__ src, __half* __restrict__ dh, int n4)
{
    int i = blockIdx.x * blockDim.x + threadIdx.x;
    if (i >= n4) return;
    float4 v = ((const float4*)src)[i];
    ((__half2*)dh)[2 * i + 0] = __halves2half2(__float2half_rn(v.x), __float2half_rn(v.y));
    ((__half2*)dh)[2 * i + 1] = __halves2half2(__float2half_rn(v.z), __float2half_rn(v.w));
}

// ---------------------------------------------------------------------------
// Counting sort of edges by dst: zero -> histogram -> scan -> scatter
// ---------------------------------------------------------------------------
__global__ void zero_cnt_kernel()
{
    int i = blockIdx.x * blockDim.x + threadIdx.x;
    if (i < N_NODES) g_cnt[i] = 0;
}

__global__ void hist_kernel(const int* __restrict__ dst)
{
    int e = blockIdx.x * blockDim.x + threadIdx.x;
    if (e < N_EDGES) atomicAdd(&g_cnt[dst[e]], 1);
}

__global__ void __launch_bounds__(1024) scan_kernel()
{
    __shared__ int part[1024];
    const int tid = threadIdx.x;
    const int base = tid * 32;
    int local[32];
    int s = 0;
    #pragma unroll
    for (int i = 0; i < 32; i++) { local[i] = g_cnt[base + i]; s += local[i]; }
    part[tid] = s;
    __syncthreads();
    for (int off = 1; off < 1024; off <<= 1) {
        int t = (tid >= off) ? part[tid - off] : 0;
        __syncthreads();
        part[tid] += t;
        __syncthreads();
    }
    int run = part[tid] - s;   // exclusive prefix
    #pragma unroll
    for (int i = 0; i < 32; i++) {
        g_start[base + i] = run;
        g_cursor[base + i] = run;
        run += local[i];
    }
}

__global__ void scatter_kernel(const int* __restrict__ src, const int* __restrict__ dst,
                               const int* __restrict__ rel)
{
    int e = blockIdx.x * blockDim.x + threadIdx.x;
    if (e >= N_EDGES) return;
    int pos = atomicAdd(&g_cursor[dst[e]], 1);
    g_ssrc[pos] = src[e];
    g_srel[pos] = rel[e];
}

// ---------------------------------------------------------------------------
// Edge aggregation in INPUT space: z[d,b,:] = sum_{e: dst=d} comp[rel_e,b]*h[src_e,:]
// One warp per dst node, dst-sorted edge list. Per edge per lane: ONE uint4
// gather of h (L2-resident 16MB) + 24 FMAs into register accumulators.
// Edges batched x4 for MLP.
// ---------------------------------------------------------------------------
__device__ __forceinline__ void agg_q(float* a0, float* a1, float* a2,
                                      uint4 q, float c0, float c1, float c2)
{
    float2 v;
    v = __half22float2(*(__half2*)&q.x);
    a0[0] = fmaf(c0, v.x, a0[0]); a0[1] = fmaf(c0, v.y, a0[1]);
    a1[0] = fmaf(c1, v.x, a1[0]); a1[1] = fmaf(c1, v.y, a1[1]);
    a2[0] = fmaf(c2, v.x, a2[0]); a2[1] = fmaf(c2, v.y, a2[1]);
    v = __half22float2(*(__half2*)&q.y);
    a0[2] = fmaf(c0, v.x, a0[2]); a0[3] = fmaf(c0, v.y, a0[3]);
    a1[2] = fmaf(c1, v.x, a1[2]); a1[3] = fmaf(c1, v.y, a1[3]);
    a2[2] = fmaf(c2, v.x, a2[2]); a2[3] = fmaf(c2, v.y, a2[3]);
    v = __half22float2(*(__half2*)&q.z);
    a0[4] = fmaf(c0, v.x, a0[4]); a0[5] = fmaf(c0, v.y, a0[5]);
    a1[4] = fmaf(c1, v.x, a1[4]); a1[5] = fmaf(c1, v.y, a1[5]);
    a2[4] = fmaf(c2, v.x, a2[4]); a2[5] = fmaf(c2, v.y, a2[5]);
    v = __half22float2(*(__half2*)&q.w);
    a0[6] = fmaf(c0, v.x, a0[6]); a0[7] = fmaf(c0, v.y, a0[7]);
    a1[6] = fmaf(c1, v.x, a1[6]); a1[7] = fmaf(c1, v.y, a1[7]);
    a2[6] = fmaf(c2, v.x, a2[6]); a2[7] = fmaf(c2, v.y, a2[7]);
}

__global__ void __launch_bounds__(256) edge_agg_kernel(const float* __restrict__ comp)
{
    const int d    = blockIdx.x * 8 + (threadIdx.x >> 5);
    const int lane = threadIdx.x & 31;

    float a0[8] = {}, a1[8] = {}, a2[8] = {};

    const int beg = g_start[d];
    const int num = g_cnt[d];
    const uint4* hp = (const uint4*)g_h;     // 32 uint4 per node row

    int i = 0;
    for (; i + 4 <= num; i += 4) {
        int s0 = g_ssrc[beg + i + 0], s1 = g_ssrc[beg + i + 1];
        int s2 = g_ssrc[beg + i + 2], s3 = g_ssrc[beg + i + 3];
        int r0 = g_srel[beg + i + 0], r1 = g_srel[beg + i + 1];
        int r2 = g_srel[beg + i + 2], r3 = g_srel[beg + i + 3];
        uint4 q0 = __ldg(hp + (size_t)s0 * 32 + lane);
        uint4 q1 = __ldg(hp + (size_t)s1 * 32 + lane);
        uint4 q2 = __ldg(hp + (size_t)s2 * 32 + lane);
        uint4 q3 = __ldg(hp + (size_t)s3 * 32 + lane);
        agg_q(a0, a1, a2, q0, __ldg(comp + r0 * 3), __ldg(comp + r0 * 3 + 1), __ldg(comp + r0 * 3 + 2));
        agg_q(a0, a1, a2, q1, __ldg(comp + r1 * 3), __ldg(comp + r1 * 3 + 1), __ldg(comp + r1 * 3 + 2));
        agg_q(a0, a1, a2, q2, __ldg(comp + r2 * 3), __ldg(comp + r2 * 3 + 1), __ldg(comp + r2 * 3 + 2));
        agg_q(a0, a1, a2, q3, __ldg(comp + r3 * 3), __ldg(comp + r3 * 3 + 1), __ldg(comp + r3 * 3 + 2));
    }
    for (; i < num; i++) {
        int s = g_ssrc[beg + i];
        int r = g_srel[beg + i];
        uint4 q = __ldg(hp + (size_t)s * 32 + lane);
        agg_q(a0, a1, a2, q, __ldg(comp + r * 3), __ldg(comp + r * 3 + 1), __ldg(comp + r * 3 + 2));
    }

    // Store z[d][b][8*lane..8*lane+7] as fp16
    __half* zp = g_z + (size_t)d * KDIM + 8 * lane;
    uint4 o;
    *(__half2*)&o.x = __floats2half2_rn(a0[0], a0[1]); *(__half2*)&o.y = __floats2half2_rn(a0[2], a0[3]);
    *(__half2*)&o.z = __floats2half2_rn(a0[4], a0[5]); *(__half2*)&o.w = __floats2half2_rn(a0[6], a0[7]);
    *(uint4*)zp = o;
    *(__half2*)&o.x = __floats2half2_rn(a1[0], a1[1]); *(__half2*)&o.y = __floats2half2_rn(a1[2], a1[3]);
    *(__half2*)&o.z = __floats2half2_rn(a1[4], a1[5]); *(__half2*)&o.w = __floats2half2_rn(a1[6], a1[7]);
    *(uint4*)(zp + 256) = o;
    *(__half2*)&o.x = __floats2half2_rn(a2[0], a2[1]); *(__half2*)&o.y = __floats2half2_rn(a2[2], a2[3]);
    *(__half2*)&o.z = __floats2half2_rn(a2[4], a2[5]); *(__half2*)&o.w = __floats2half2_rn(a2[6], a2[7]);
    *(uint4*)(zp + 512) = o;
}

// ---------------------------------------------------------------------------
// Tensor-core GEMM: out[m,n] = relu(bias[n] + z[m,:] . B[:,n]), K=768.
// CTA: 128x64, K chunked by 64 (12 chunks), 2-stage cp.async, 3 CTAs/SM.
// 8 warps as 4(M) x 2(N): warp tile 32x32, mma.m16n8k16. Fused bias+ReLU.
// ---------------------------------------------------------------------------
#define SAROW 144u                 // 64 halfs + 16B pad
#define SBROW 144u
#define OFF_B  18432u              // 128*144
#define STAGE_B 27648u             // A 18432 | B 9216
#define GEMM_SMEM (2 * 27648)

__device__ __forceinline__ void ldm_x4(uint32_t* r, uint32_t addr) {
    asm volatile("ldmatrix.sync.aligned.m8n8.x4.shared.b16 {%0,%1,%2,%3}, [%4];"
                 : "=r"(r[0]), "=r"(r[1]), "=r"(r[2]), "=r"(r[3]) : "r"(addr));
}
__device__ __forceinline__ void ldm_x4t(uint32_t* r, uint32_t addr) {
    asm volatile("ldmatrix.sync.aligned.m8n8.x4.trans.shared.b16 {%0,%1,%2,%3}, [%4];"
                 : "=r"(r[0]), "=r"(r[1]), "=r"(r[2]), "=r"(r[3]) : "r"(addr));
}
__device__ __forceinline__ void mma16816(float* c, const uint32_t* a, const uint32_t* b) {
    asm volatile("mma.sync.aligned.m16n8k16.row.col.f32.f16.f16.f32 "
                 "{%0,%1,%2,%3}, {%4,%5,%6,%7}, {%8,%9}, {%0,%1,%2,%3};"
                 : "+f"(c[0]), "+f"(c[1]), "+f"(c[2]), "+f"(c[3])
                 : "r"(a[0]), "r"(a[1]), "r"(a[2]), "r"(a[3]), "r"(b[0]), "r"(b[1]));
}
__device__ __forceinline__ void cpa16(uint32_t dst, const void* src) {
    asm volatile("cp.async.cg.shared.global [%0], [%1], 16;" :: "r"(dst), "l"(src) : "memory");
}

__device__ __forceinline__ void gemm_load_chunk(uint32_t sb, int s, int m0, int n0, int c, int tid)
{
    const uint32_t so = sb + (uint32_t)s * STAGE_B;
    const int k0 = c << 6;
    // A (= z): 128 rows x 64 halfs (8 x 16B per row)
    #pragma unroll
    for (int i = 0; i < 4; i++) {
        int idx = tid + (i << 8);
        int row = idx >> 3, ch = idx & 7;
        size_t goff = (size_t)(m0 + row) * KDIM + k0 + (ch << 3);
        cpa16(so + (uint32_t)row * SAROW + (uint32_t)(ch << 4), g_z + goff);
    }
    // B: 64 k-rows x 64 halfs
    #pragma unroll
    for (int i = 0; i < 2; i++) {
        int idx = tid + (i << 8);
        int row = idx >> 3, ch = idx & 7;
        size_t goff = (size_t)(k0 + row) * OUT_F + n0 + (ch << 3);
        cpa16(so + OFF_B + (uint32_t)row * SBROW + (uint32_t)(ch << 4), g_Bh + goff);
    }
    asm volatile("cp.async.commit_group;" ::: "memory");
}

__global__ void __launch_bounds__(256, 3) gemm_tc_kernel(
    const float* __restrict__ bias, float* __restrict__ out)
{
    extern __shared__ char smem[];
    const uint32_t sb = smem_u32(smem);
    const int tid  = threadIdx.x;
    const int wid  = tid >> 5;
    const int lane = tid & 31;
    const int wm = wid >> 1;          // 0..3 (M)
    const int wn = wid & 1;           // 0..1 (N)
    const int n0 = blockIdx.x << 6;
    const int m0 = blockIdx.y << 7;

    const uint32_t a_lane = (uint32_t)((lane & 15) * SAROW + (lane >> 4) * 16) + (uint32_t)(wm * 32) * SAROW;
    const uint32_t b_lane = (uint32_t)((lane & 15) * SBROW + (lane >> 4) * 16) + (uint32_t)(wn * 64);

    float acc[2][4][4];
    #pragma unroll
    for (int mt = 0; mt < 2; mt++)
        #pragma unroll
        for (int nt = 0; nt < 4; nt++)
            #pragma unroll
            for (int q = 0; q < 4; q++) acc[mt][nt][q] = 0.0f;

    gemm_load_chunk(sb, 0, m0, n0, 0, tid);

    for (int c = 0; c < 12; c++) {
        if (c + 1 < 12) {
            gemm_load_chunk(sb, (c + 1) & 1, m0, n0, c + 1, tid);
            asm volatile("cp.async.wait_group 1;" ::: "memory");
        } else {
            asm volatile("cp.async.wait_group 0;" ::: "memory");
        }
        __syncthreads();

        const uint32_t so = sb + (uint32_t)(c & 1) * STAGE_B;
        #pragma unroll
        for (int kk = 0; kk < 4; kk++) {
            uint32_t ah[2][4];
            #pragma unroll
            for (int mt = 0; mt < 2; mt++)
                ldm_x4(ah[mt], so + a_lane + (uint32_t)(mt * 16) * SAROW + (uint32_t)(kk * 32));
            #pragma unroll
            for (int p = 0; p < 2; p++) {
                uint32_t bh[4];
                ldm_x4t(bh, so + OFF_B + b_lane + (uint32_t)(kk * 16) * SBROW + (uint32_t)(p * 32));
                #pragma unroll
                for (int s = 0; s < 2; s++) {
                    const int nt = p * 2 + s;
                    #pragma unroll
                    for (int mt = 0; mt < 2; mt++)
                        mma16816(acc[mt][nt], ah[mt], bh + 2 * s);
                }
            }
        }
        __syncthreads();
    }

    // Epilogue: out = relu(acc + bias), fp32, written exactly once per element
    #pragma unroll
    for (int mt = 0; mt < 2; mt++) {
        int row0 = m0 + wm * 32 + mt * 16 + (lane >> 2);
        #pragma unroll
        for (int nt = 0; nt < 4; nt++) {
            int col = n0 + wn * 32 + nt * 8 + (lane & 3) * 2;
            float b0 = __ldg(bias + col), b1 = __ldg(bias + col + 1);
            float2 v0 = make_float2(fmaxf(acc[mt][nt][0] + b0, 0.f), fmaxf(acc[mt][nt][1] + b1, 0.f));
            float2 v1 = make_float2(fmaxf(acc[mt][nt][2] + b0, 0.f), fmaxf(acc[mt][nt][3] + b1, 0.f));
            *(float2*)(out + (size_t)row0 * OUT_F + col) = v0;
            *(float2*)(out + (size_t)(row0 + 8) * OUT_F + col) = v1;
        }
    }
}

// ---------------------------------------------------------------------------
// Launch
// ---------------------------------------------------------------------------
extern "C" void kernel_launch(void* const* d_in, const int* in_sizes, int n_in,
                              void* d_out, int out_size)
{
    const float* text  = (const float*)d_in[0];   // [64,512,256]
    const int*   src   = (const int*)  d_in[1];   // [E]
    const int*   dst   = (const int*)  d_in[2];   // [E]
    const int*   rel   = (const int*)  d_in[3];   // [E]
    const float* bases = (const float*)d_in[4];   // [3,256,256]
    const float* comp  = (const float*)d_in[5];   // [40,3]
    const float* bias  = (const float*)d_in[6];   // [256]
    float* out = (float*)d_out;                   // [64,512,256]

    cudaFuncSetAttribute(gemm_tc_kernel, cudaFuncAttributeMaxDynamicSharedMemorySize, GEMM_SMEM);

    // 1. fp16 converts: h and stacked bases [(b,i)][o]
    __half *hh, *bh;
    cudaGetSymbolAddress((void**)&hh, g_h);
    cudaGetSymbolAddress((void**)&bh, g_Bh);
    split_h_kernel<<<(N_NODES * IN_F / 4 + 255) / 256, 256>>>(text, hh, N_NODES * IN_F / 4);
    split_h_kernel<<<(KDIM * OUT_F / 4 + 255) / 256, 256>>>(bases, bh, KDIM * OUT_F / 4);

    // 2. counting sort of edges by dst
    zero_cnt_kernel<<<N_NODES / 256, 256>>>();
    hist_kernel<<<N_EDGES / 256, 256>>>(dst);
    scan_kernel<<<1, 1024>>>();
    scatter_kernel<<<N_EDGES / 256, 256>>>(src, dst, rel);

    // 3. aggregate in input space: z[d,b,:] = sum comp[rel,b]*h[src]
    edge_agg_kernel<<<N_NODES / 8, 256>>>(comp);

    // 4. out = relu(z @ B_stacked + bias) on the tensor pipe
    gemm_tc_kernel<<<dim3(OUT_F / 64, N_NODES / 128), 256, GEMM_SMEM>>>(bias, out);
}